// round 15
// baseline (speedup 1.0000x reference)
#include <cuda_runtime.h>

// out[b,s,f,o] = sum_{t,k,c} x[b, s+t-2, f*(k+1), c] * W[t,k,c,o],  f*(k+1) < F
// x [4,1024,512,4] f32, W [5,4,4,4] f32, out [4,1024,512,4] f32.
//
// R15: R13 (smem tile, LDS gathers, o-pair FFMA2, in-block warp balance,
//      direct-memcpy constant weights) + SKEWED tile layout sigma(f)=f+(f>>3)
//      (row stride 576): bank-conflict degree per harmonic stride becomes
//      {1,1,2,1} instead of {1,2,1,4} -> ~40% fewer gather crossbar cycles
//      on the heavy warps that set block duration. 72KB tile, 3 blocks/SM.

#define B_  4
#define S_  1024
#define F_  512
#define U_  4
#define NT  5
#define NK  4
#define TPB 256
#define RS  576                    // skewed row stride in float4 units

typedef unsigned long long u64;

// raw layout: WcR[t][k][c] = (W[t][k][c][0..1], W[t][k][c][2..3]) as o-pairs
__constant__ ulonglong2 WcR[NT][NK][4];

__device__ __forceinline__ u64 fma2(u64 a, u64 b, u64 c) {
    u64 d;
    asm("fma.rn.f32x2 %0, %1, %2, %3;" : "=l"(d) : "l"(a), "l"(b), "l"(c));
    return d;
}
__device__ __forceinline__ u64 dup2(float v) {
    u64 d;
    asm("mov.b64 %0, {%1, %1};" : "=l"(d) : "f"(v));
    return d;
}
__device__ __forceinline__ int swz(int f) { return f + (f >> 3); }

struct Row { u64 c0, c1, c2, c3; };

__device__ __forceinline__ Row loadRow(const float4* __restrict__ p) {
    float4 v = *p;
    Row r;
    r.c0 = dup2(v.x); r.c1 = dup2(v.y); r.c2 = dup2(v.z); r.c3 = dup2(v.w);
    return r;
}

// one harmonic k: 5 taps x 4 outputs over ring-buffered rows of `col`
// (col already points at the swizzled column; rows at stride RS)
__device__ __forceinline__ void harmonic(
    const float4* __restrict__ col, int k, u64 acc[U_][2])
{
    Row w4[4];
#pragma unroll
    for (int m = 0; m < 4; ++m) w4[m] = loadRow(col + m * RS);

#pragma unroll
    for (int t = 0; t < NT; ++t) {
        ulonglong2 q0 = WcR[t][k][0];
        ulonglong2 q1 = WcR[t][k][1];
        ulonglong2 q2 = WcR[t][k][2];
        ulonglong2 q3 = WcR[t][k][3];
#pragma unroll
        for (int j = 0; j < U_; ++j) {
            Row rv = w4[(t + j) & 3];
            acc[j][0] = fma2(rv.c0, q0.x, acc[j][0]);
            acc[j][1] = fma2(rv.c0, q0.y, acc[j][1]);
            acc[j][0] = fma2(rv.c1, q1.x, acc[j][0]);
            acc[j][1] = fma2(rv.c1, q1.y, acc[j][1]);
            acc[j][0] = fma2(rv.c2, q2.x, acc[j][0]);
            acc[j][1] = fma2(rv.c2, q2.y, acc[j][1]);
            acc[j][0] = fma2(rv.c3, q3.x, acc[j][0]);
            acc[j][1] = fma2(rv.c3, q3.y, acc[j][1]);
        }
        if (t < NT - 1) w4[t & 3] = loadRow(col + (t + 4) * RS);
    }
}

__device__ __forceinline__ void store4(
    float4* __restrict__ o4, const u64 acc[U_][2])
{
#pragma unroll
    for (int j = 0; j < U_; ++j) {
        float2 lo = reinterpret_cast<const float2&>(acc[j][0]);
        float2 hi = reinterpret_cast<const float2&>(acc[j][1]);
        o4[(size_t)j * F_] = make_float4(lo.x, lo.y, hi.x, hi.y);
    }
}

__global__ __launch_bounds__(TPB, 3) void harm_conv_kernel(
    const float* __restrict__ x,
    float* __restrict__ out)
{
    extern __shared__ float4 tile[];              // [8][RS] skewed rows

    int bx = blockIdx.x;
    int sb = bx & (S_ / U_ - 1);
    int b  = bx >> 8;
    int s0 = sb * U_;
    int tid = threadIdx.x;

    const float4* __restrict__ xb =
        reinterpret_cast<const float4*>(x) + (size_t)b * S_ * F_;

    int sw1 = swz(tid);                           // col tid
    int sw2 = swz(tid + TPB);                     // col tid+256

    // ── stage 8 full rows (each thread: 2 cols x 8 rows), coalesced LDG ──
    if (sb > 0 && sb < S_ / U_ - 1) {
        const float4* __restrict__ src = xb + (size_t)(s0 - 2) * F_ + tid;
#pragma unroll
        for (int i = 0; i < U_ + 4; ++i) {
            tile[i * RS + sw1] = src[(size_t)i * F_];
            tile[i * RS + sw2] = src[(size_t)i * F_ + TPB];
        }
    } else {
#pragma unroll
        for (int i = 0; i < U_ + 4; ++i) {
            int sp = s0 + i - 2;
            if (sp >= 0 && sp < S_) {
                tile[i * RS + sw1] = xb[(size_t)sp * F_ + tid];
                tile[i * RS + sw2] = xb[(size_t)sp * F_ + tid + TPB];
            } else {
                tile[i * RS + sw1] = make_float4(0.f, 0.f, 0.f, 0.f);
                tile[i * RS + sw2] = make_float4(0.f, 0.f, 0.f, 0.f);
            }
        }
    }
    __syncthreads();

    float4* __restrict__ obase =
        reinterpret_cast<float4*>(out) + ((size_t)(b * S_ + s0)) * F_;

    // ── heavy chunk: f1 = tid (f < 256), full harmonic loop ──
    int f1 = tid;
    {
        u64 acc[U_][2];
#pragma unroll
        for (int j = 0; j < U_; ++j) { acc[j][0] = 0ull; acc[j][1] = 0ull; }

        for (int k = 0; k < NK; ++k) {
            int fk = f1 * (k + 1);
            if (fk >= F_) break;                  // near-coherent within warp
            harmonic(tile + swz(fk), k, acc);
        }
        store4(obase + f1, acc);
    }

    // ── light chunk: f2 = tid + 256 (f >= 256), k = 0 only ──
    int f2 = tid + TPB;
    {
        u64 acc[U_][2];
#pragma unroll
        for (int j = 0; j < U_; ++j) { acc[j][0] = 0ull; acc[j][1] = 0ull; }

        harmonic(tile + sw2, 0, acc);
        store4(obase + f2, acc);
    }
}

extern "C" void kernel_launch(void* const* d_in, const int* in_sizes, int n_in,
                              void* d_out, int out_size)
{
    const float* x = (const float*)d_in[0];
    const float* W = (const float*)d_in[1];
    float* out = (float*)d_out;

    const int SMEM = (U_ + 4) * RS * 16;          // 72 KB

    (void)cudaFuncSetAttribute(harm_conv_kernel,
                               cudaFuncAttributeMaxDynamicSharedMemorySize,
                               SMEM);

    // raw W layout IS the o-pair packed layout: direct copy, no transpose node
    cudaMemcpyToSymbolAsync(WcR, W, NT * NK * 16 * sizeof(float), 0,
                            cudaMemcpyDeviceToDevice, 0);

    int blocks = B_ * (S_ / U_);                  // 1024 uniform blocks
    harm_conv_kernel<<<blocks, TPB, SMEM>>>(x, out);
}